// round 3
// baseline (speedup 1.0000x reference)
#include <cuda_runtime.h>
#include <stdint.h>

// Problem constants
#define B_   8
#define F_   64
#define E_   50000
#define CO_  128
#define KW_  5
#define KK_  320      // F_*KW_ (joint contraction dim, kappa = f*5+k)
#define TE_  128      // edges per CTA
#define TEP_ 132      // padded row stride for Gs (132 mod 32 == 4 -> conflict-free)
#define KC_  40       // k-chunk staged in smem
#define NT_  256      // threads per CTA

// Scratch: transposed x (B,E,F), transposed W (kappa-major), dtype flag
__device__ __align__(16) float g_xt[(size_t)B_ * E_ * F_];   // 102.4 MB
__device__ __align__(16) float g_wt[KK_ * CO_];              // 160 KB
__device__ int g_idx64;   // 1 if gemm buffer is int64, 0 if int32

// ---------------------------------------------------------------------------
// Detect gemm dtype: for int64 values in [0, E), every odd 32-bit word is 0.
// For int32 random data in [0, E), 2048 consecutive odd words all-zero is
// impossible. One block, OR-reduce, write flag.
// ---------------------------------------------------------------------------
__global__ void detect_dtype_kernel(const unsigned int* __restrict__ g) {
    __shared__ int s_nonzero;
    if (threadIdx.x == 0) s_nonzero = 0;
    __syncthreads();
    unsigned acc = 0;
    #pragma unroll
    for (int i = 0; i < 8; i++)
        acc |= g[(threadIdx.x + i * 256) * 2 + 1];   // odd words 1,3,...,4095
    if (acc) atomicOr(&s_nonzero, 1);
    __syncthreads();
    if (threadIdx.x == 0) g_idx64 = (s_nonzero == 0) ? 1 : 0;
}

// ---------------------------------------------------------------------------
// x (B,F,E) -> xt (B,E,F): makes each edge's feature row contiguous (256B)
// ---------------------------------------------------------------------------
__global__ void transpose_kernel(const float* __restrict__ x) {
    __shared__ float t[32][33];
    int b  = blockIdx.z;
    int f0 = blockIdx.y * 32;
    int e0 = blockIdx.x * 32;

    int e = e0 + threadIdx.x;
    if (e < E_)
        t[threadIdx.y][threadIdx.x] = x[((size_t)b * F_ + f0 + threadIdx.y) * E_ + e];
    __syncthreads();

    int f  = f0 + threadIdx.x;
    int ee = e0 + threadIdx.y;
    if (ee < E_)
        g_xt[((size_t)b * E_ + ee) * F_ + f] = t[threadIdx.x][threadIdx.y];
}

// ---------------------------------------------------------------------------
// W (Cout, F, 1, K) -> Wt[kappa][o]  (kappa = f*5+k), so chunk loads coalesce
// ---------------------------------------------------------------------------
__global__ void wt_kernel(const float* __restrict__ W) {
    int i = blockIdx.x * blockDim.x + threadIdx.x;
    if (i < KK_ * CO_) {
        int o  = i & (CO_ - 1);
        int kk = i >> 7;
        g_wt[i] = W[o * KK_ + kk];
    }
}

// ---------------------------------------------------------------------------
// Main: per (batch, 128-edge tile): gather+combine into Gs[320][132], then
// register-blocked GEMM 128o x 128e with f32x2 packed FMAs.
// ---------------------------------------------------------------------------
__global__ __launch_bounds__(NT_) void meshconv_kernel(
    const void*  __restrict__ gemm_raw,
    const float* __restrict__ bias,
    float*       __restrict__ out)
{
    extern __shared__ float smem[];
    float* Gs = smem;                 // [KK_][TEP_]  = 168,960 B
    float* Ws = smem + KK_ * TEP_;    // [KC_][CO_]   =  20,480 B

    const int tid = threadIdx.x;
    const int b   = blockIdx.y;
    const int e0  = blockIdx.x * TE_;

    // ---------------- gather + combine phase ----------------
    {
        int e    = tid & (TE_ - 1);        // local edge 0..127
        int half = tid >> 7;               // 0/1 -> f offset 0/32
        int eg   = e0 + e; if (eg >= E_) eg = E_ - 1;   // clamp tail (stores OK: dup rows, out-store guarded)

        size_t gidx = ((size_t)b * E_ + eg) * 4;
        int n1, n2, n3, n4;
        if (g_idx64) {
            const long long* gp = (const long long*)gemm_raw + gidx;
            n1 = (int)gp[0]; n2 = (int)gp[1]; n3 = (int)gp[2]; n4 = (int)gp[3];
        } else {
            const int* gp = (const int*)gemm_raw + gidx;
            n1 = gp[0]; n2 = gp[1]; n3 = gp[2]; n4 = gp[3];
        }

        const float4* r0 = (const float4*)(g_xt + ((size_t)b * E_ + eg) * F_) + half * 8;
        const float4* r1 = (const float4*)(g_xt + ((size_t)b * E_ + n1) * F_) + half * 8;
        const float4* r2 = (const float4*)(g_xt + ((size_t)b * E_ + n2) * F_) + half * 8;
        const float4* r3 = (const float4*)(g_xt + ((size_t)b * E_ + n3) * F_) + half * 8;
        const float4* r4 = (const float4*)(g_xt + ((size_t)b * E_ + n4) * F_) + half * 8;

        int fbase = half * 32;
        #pragma unroll
        for (int i = 0; i < 8; i++) {
            float4 v0 = r0[i], v1 = r1[i], v2 = r2[i], v3 = r3[i], v4 = r4[i];
            int f = fbase + i * 4;
            {
                float* gc = Gs + (size_t)(f + 0) * KW_ * TEP_ + e;
                gc[0*TEP_] = v0.x;
                gc[1*TEP_] = v1.x + v3.x;
                gc[2*TEP_] = v2.x + v4.x;
                gc[3*TEP_] = fabsf(v1.x - v3.x);
                gc[4*TEP_] = fabsf(v2.x - v4.x);
            }
            {
                float* gc = Gs + (size_t)(f + 1) * KW_ * TEP_ + e;
                gc[0*TEP_] = v0.y;
                gc[1*TEP_] = v1.y + v3.y;
                gc[2*TEP_] = v2.y + v4.y;
                gc[3*TEP_] = fabsf(v1.y - v3.y);
                gc[4*TEP_] = fabsf(v2.y - v4.y);
            }
            {
                float* gc = Gs + (size_t)(f + 2) * KW_ * TEP_ + e;
                gc[0*TEP_] = v0.z;
                gc[1*TEP_] = v1.z + v3.z;
                gc[2*TEP_] = v2.z + v4.z;
                gc[3*TEP_] = fabsf(v1.z - v3.z);
                gc[4*TEP_] = fabsf(v2.z - v4.z);
            }
            {
                float* gc = Gs + (size_t)(f + 3) * KW_ * TEP_ + e;
                gc[0*TEP_] = v0.w;
                gc[1*TEP_] = v1.w + v3.w;
                gc[2*TEP_] = v2.w + v4.w;
                gc[3*TEP_] = fabsf(v1.w - v3.w);
                gc[4*TEP_] = fabsf(v2.w - v4.w);
            }
        }
    }
    __syncthreads();

    // ---------------- GEMM phase ----------------
    const int tx = tid & 15;   // 16 edge-groups of 8
    const int ty = tid >> 4;   // 16 o-groups of 8

    unsigned long long acc[8][4];
    #pragma unroll
    for (int m = 0; m < 8; m++)
        #pragma unroll
        for (int j = 0; j < 4; j++)
            acc[m][j] = 0ull;   // two packed +0.0f

    const float4* Wt4 = (const float4*)g_wt;
    float4*       Ws4 = (float4*)Ws;

    #pragma unroll 1
    for (int c = 0; c < KK_ / KC_; c++) {
        // stage W chunk: KC_*CO_/4 = 1280 float4 over 256 threads -> 5 each, coalesced
        #pragma unroll
        for (int i = 0; i < 5; i++)
            Ws4[tid + i * 256] = Wt4[c * (KC_ * CO_ / 4) + tid + i * 256];
        __syncthreads();

        #pragma unroll 8
        for (int k = 0; k < KC_; k++) {
            const float* grow = Gs + (size_t)(c * KC_ + k) * TEP_ + tx * 8;
            ulonglong2 gA = *(const ulonglong2*)grow;         // e pairs 0,1
            ulonglong2 gB = *(const ulonglong2*)(grow + 4);   // e pairs 2,3
            unsigned long long g[4] = {gA.x, gA.y, gB.x, gB.y};

            const float* wrow = Ws + k * CO_ + ty * 8;
            float4 wa = *(const float4*)wrow;
            float4 wb = *(const float4*)(wrow + 4);
            float wf[8] = {wa.x, wa.y, wa.z, wa.w, wb.x, wb.y, wb.z, wb.w};

            unsigned long long wd[8];
            #pragma unroll
            for (int m = 0; m < 8; m++)
                asm("mov.b64 %0, {%1, %1};" : "=l"(wd[m]) : "r"(__float_as_uint(wf[m])));

            #pragma unroll
            for (int m = 0; m < 8; m++)
                #pragma unroll
                for (int j = 0; j < 4; j++)
                    asm("fma.rn.f32x2 %0, %1, %2, %3;"
                        : "=l"(acc[m][j])
                        : "l"(wd[m]), "l"(g[j]), "l"(acc[m][j]));
        }
        __syncthreads();
    }

    // ---------------- epilogue: unpack, add bias, store ----------------
    #pragma unroll
    for (int m = 0; m < 8; m++) {
        int o = ty * 8 + m;
        float bv = __ldg(bias + o);
        float r[8];
        #pragma unroll
        for (int j = 0; j < 4; j++) {
            r[2*j]     = __uint_as_float((unsigned)(acc[m][j] & 0xffffffffull)) + bv;
            r[2*j + 1] = __uint_as_float((unsigned)(acc[m][j] >> 32)) + bv;
        }
        int e = e0 + tx * 8;
        size_t base = ((size_t)b * CO_ + o) * E_ + e;
        if (e + 7 < E_) {
            *(float4*)(out + base)     = make_float4(r[0], r[1], r[2], r[3]);
            *(float4*)(out + base + 4) = make_float4(r[4], r[5], r[6], r[7]);
        } else {
            #pragma unroll
            for (int q = 0; q < 8; q++)
                if (e + q < E_) out[base + q] = r[q];
        }
    }
}

// ---------------------------------------------------------------------------
extern "C" void kernel_launch(void* const* d_in, const int* in_sizes, int n_in,
                              void* d_out, int out_size) {
    const float* x    = (const float*)d_in[0];
    const void*  gemm = d_in[1];
    const float* W    = (const float*)d_in[2];
    const float* bias = (const float*)d_in[3];
    float*       out  = (float*)d_out;

    // Pass 0: detect gemm dtype (int32 vs int64)
    detect_dtype_kernel<<<1, 256>>>((const unsigned int*)gemm);

    // Pass 1: transpose x into g_xt
    dim3 tb(32, 32);
    dim3 tg((E_ + 31) / 32, F_ / 32, B_);
    transpose_kernel<<<tg, tb>>>(x);

    // Pass 2: transpose W into g_wt
    wt_kernel<<<(KK_ * CO_ + 255) / 256, 256>>>(W);

    // Pass 3: main fused gather + GEMM
    int smem_bytes = (KK_ * TEP_ + KC_ * CO_) * (int)sizeof(float);  // 189,440 B
    cudaFuncSetAttribute(meshconv_kernel,
                         cudaFuncAttributeMaxDynamicSharedMemorySize, smem_bytes);
    dim3 mg((E_ + TE_ - 1) / TE_, B_);
    meshconv_kernel<<<mg, NT_, smem_bytes>>>(gemm, bias, out);
}

// round 7
// speedup vs baseline: 2.9557x; 2.9557x over previous
#include <cuda_runtime.h>
#include <stdint.h>

// ---------------- problem constants ----------------
#define B_   8
#define F_   64
#define E_   50000
#define CO_  128
#define KK_  320         // F*5 contraction dim (kappa' = q*64 + f ordering)
#define TN_  128         // edges per tile (MMA N)
#define NT_  256         // threads per CTA
#define TILES_PB_ 391    // ceil(50000/128)
#define NTILES_   (TILES_PB_ * B_)
#define NSTEP_    40     // 320 / 8 (tf32 K per MMA)

#define TMEM_D_  0       // D: cols 0..127
#define TMEM_A_  128     // A: cols 128..447
#define WS_STR_  324     // W smem staging row stride (floats); 324%32==4, 16B-aligned rows

// idesc kind::tf32: c=F32(1<<4), a=TF32(2<<7), b=TF32(2<<10), N=128(16<<17), M=128(8<<24)
#define IDESC_ 0x8200910u

__device__ __align__(16) float g_xt[(size_t)B_ * E_ * F_];   // x transposed (B,E,F)
__device__ int g_idx64;

// Arch-feature gate: tcgen05 is only legal in the sm_103a-specific pass.
// The harness fatbin also runs a generic compute_103 pass; there the kernel
// body compiles to an empty stub that is never selected at runtime on GB300.
#if defined(__CUDA_ARCH_FEAT_SM103_ALL)
#define TC_OK_ 1
#else
#define TC_OK_ 0
#endif

// ---------------- PTX helpers (generic, legal everywhere) ----------------
__device__ __forceinline__ uint32_t smem_u32(const void* p) {
    uint32_t a;
    asm("{ .reg .u64 t; cvta.to.shared.u64 t, %1; cvt.u32.u64 %0, t; }" : "=r"(a) : "l"(p));
    return a;
}
__device__ __forceinline__ uint32_t elect1() {
    uint32_t p;
    asm volatile("{ .reg .pred p; elect.sync _|p, 0xFFFFFFFF; selp.b32 %0, 1, 0, p; }" : "=r"(p));
    return p;
}
__device__ __forceinline__ float f2t(float x) {   // round-to-nearest tf32
    uint32_t u;
    asm("cvt.rna.tf32.f32 %0, %1;" : "=r"(u) : "f"(x));
    return __uint_as_float(u);
}

#define MB_INIT(mb, c)    asm volatile("mbarrier.init.shared.b64 [%0], %1;" :: "r"(mb), "r"(c) : "memory")
#define MB_INVAL(mb)      asm volatile("mbarrier.inval.shared.b64 [%0];" :: "r"(mb) : "memory")

#define MB_WAIT_PARITY(mb, ph) do {                                          \
    uint32_t _m = (mb), _p = (ph), _d;                                       \
    asm volatile("{ .reg .pred p; mbarrier.try_wait.parity.acquire.cta.shared::cta.b64 p, [%1], %2; selp.b32 %0,1,0,p; }" \
                 : "=r"(_d) : "r"(_m), "r"(_p) : "memory");                  \
    if (!_d) {                                                               \
        asm volatile("{ .reg .pred P1;\n"                                    \
            "WL_%=: mbarrier.try_wait.parity.acquire.cta.shared::cta.b64 P1, [%0], %1, 0x989680;\n" \
            "@P1 bra.uni WD_%=;\n bra.uni WL_%=;\nWD_%=: }"                  \
            :: "r"(_m), "r"(_p) : "memory");                                 \
    } } while (0)

// ---------------- tcgen05 helpers (sm_103a-only; used inside guarded body) ----------------
#if TC_OK_
#define TC_ALLOC(sa, n)   asm volatile("tcgen05.alloc.cta_group::1.sync.aligned.shared::cta.b32 [%0], %1;" :: "r"(sa), "r"(n) : "memory")
#define TC_RELINQ()       asm volatile("tcgen05.relinquish_alloc_permit.cta_group::1.sync.aligned;")
#define TC_DEALLOC(t, n)  asm volatile("tcgen05.dealloc.cta_group::1.sync.aligned.b32 %0, %1;" :: "r"(t), "r"(n))
#define TC_WAIT_ST()      asm volatile("tcgen05.wait::st.sync.aligned;" ::: "memory")
#define TC_WAIT_LD()      asm volatile("tcgen05.wait::ld.sync.aligned;" ::: "memory")
#define TC_FENCE_BEFORE() asm volatile("tcgen05.fence::before_thread_sync;" ::: "memory")
#define TC_FENCE_AFTER()  asm volatile("tcgen05.fence::after_thread_sync;" ::: "memory")
#define TC_COMMIT(mb)     asm volatile("tcgen05.commit.cta_group::1.mbarrier::arrive::one.shared::cluster.b64 [%0];" :: "r"(mb) : "memory")

#define TC_ST_X32(addr, r) \
    asm volatile("tcgen05.st.sync.aligned.32x32b.x32.b32 [%0], "             \
        "{%1,%2,%3,%4,%5,%6,%7,%8,%9,%10,%11,%12,%13,%14,%15,%16,"          \
        "%17,%18,%19,%20,%21,%22,%23,%24,%25,%26,%27,%28,%29,%30,%31,%32};" \
        :: "r"(addr),                                                        \
        "r"((r)[0]),"r"((r)[1]),"r"((r)[2]),"r"((r)[3]),"r"((r)[4]),"r"((r)[5]),"r"((r)[6]),"r"((r)[7]), \
        "r"((r)[8]),"r"((r)[9]),"r"((r)[10]),"r"((r)[11]),"r"((r)[12]),"r"((r)[13]),"r"((r)[14]),"r"((r)[15]), \
        "r"((r)[16]),"r"((r)[17]),"r"((r)[18]),"r"((r)[19]),"r"((r)[20]),"r"((r)[21]),"r"((r)[22]),"r"((r)[23]), \
        "r"((r)[24]),"r"((r)[25]),"r"((r)[26]),"r"((r)[27]),"r"((r)[28]),"r"((r)[29]),"r"((r)[30]),"r"((r)[31]) \
        : "memory")

#define TC_LD_X32(r, addr) \
    asm volatile("tcgen05.ld.sync.aligned.32x32b.x32.b32 "                   \
        "{%0,%1,%2,%3,%4,%5,%6,%7,%8,%9,%10,%11,%12,%13,%14,%15,"           \
        "%16,%17,%18,%19,%20,%21,%22,%23,%24,%25,%26,%27,%28,%29,%30,%31}, [%32];" \
        : "=r"((r)[0]),"=r"((r)[1]),"=r"((r)[2]),"=r"((r)[3]),"=r"((r)[4]),"=r"((r)[5]),"=r"((r)[6]),"=r"((r)[7]), \
        "=r"((r)[8]),"=r"((r)[9]),"=r"((r)[10]),"=r"((r)[11]),"=r"((r)[12]),"=r"((r)[13]),"=r"((r)[14]),"=r"((r)[15]), \
        "=r"((r)[16]),"=r"((r)[17]),"=r"((r)[18]),"=r"((r)[19]),"=r"((r)[20]),"=r"((r)[21]),"=r"((r)[22]),"=r"((r)[23]), \
        "=r"((r)[24]),"=r"((r)[25]),"=r"((r)[26]),"=r"((r)[27]),"=r"((r)[28]),"=r"((r)[29]),"=r"((r)[30]),"=r"((r)[31]) \
        : "r"(addr))

__device__ __forceinline__ void mma_tf32_ts(uint32_t d, uint32_t a, uint64_t bdesc,
                                            uint32_t idesc, bool acc) {
    uint32_t en = acc ? 1u : 0u;
    asm volatile(
        "{\n\t.reg .pred p;\n\tsetp.ne.u32 p, %5, 0;\n\t"
        "tcgen05.mma.cta_group::1.kind::tf32 [%0], [%1], %2, %3, {%4, %4, %4, %4}, p;\n\t}"
        :: "r"(d), "r"(a), "l"(bdesc), "r"(idesc), "r"(0u), "r"(en) : "memory");
}
#endif // TC_OK_

// SW128 smem descriptor: layout=SW128(2), version=1, SBO=64 (1024B / 8-row group), LBO=1
#define DESC_BASE_ ((2ull << 61) | (1ull << 46) | (64ull << 32) | (1ull << 16))
#define MAKE_DESC(a) (DESC_BASE_ | ((uint64_t)((a) >> 4) & 0x3FFF))
#define SWZ(o) ((o) ^ (((o) >> 3) & 0x70))

// ---------------------------------------------------------------------------
// dtype detect for gemm (int64 silently downcast to int32 by JAX default)
// ---------------------------------------------------------------------------
__global__ void detect_dtype_kernel(const unsigned int* __restrict__ g) {
    __shared__ int s_nz;
    if (threadIdx.x == 0) s_nz = 0;
    __syncthreads();
    unsigned acc = 0;
    #pragma unroll
    for (int i = 0; i < 8; i++) acc |= g[(threadIdx.x + i * 256) * 2 + 1];
    if (acc) atomicOr(&s_nz, 1);
    __syncthreads();
    if (threadIdx.x == 0) g_idx64 = (s_nz == 0) ? 1 : 0;
}

// ---------------------------------------------------------------------------
// x (B,F,E) -> xt (B,E,F), 64x64 tiles, float4 both sides
// ---------------------------------------------------------------------------
__global__ __launch_bounds__(256) void transpose_kernel(const float* __restrict__ x) {
    __shared__ float t[64 * 68];
    int b  = blockIdx.y;
    int e0 = blockIdx.x * 64;
    int tid = threadIdx.x;

    if (e0 + 64 <= E_) {
        #pragma unroll
        for (int i = 0; i < 4; i++) {
            int idx = tid + i * 256;          // 1024 float4: f = idx/16, c4 = idx%16
            int f = idx >> 4, c4 = idx & 15;
            float4 v = *(const float4*)(x + ((size_t)b * F_ + f) * E_ + e0 + c4 * 4);
            *(float4*)(&t[f * 68 + c4 * 4]) = v;
        }
        __syncthreads();
        int e  = tid & 63;
        int jb = tid >> 6;                    // 0..3
        float* po = g_xt + ((size_t)b * E_ + e0 + e) * F_;
        #pragma unroll
        for (int jj = 0; jj < 4; jj++) {
            int j = jb + jj * 4;              // float4 index over f
            float4 v = make_float4(t[(j*4+0)*68 + e], t[(j*4+1)*68 + e],
                                   t[(j*4+2)*68 + e], t[(j*4+3)*68 + e]);
            *(float4*)(po + j * 4) = v;
        }
    } else {
        for (int idx = tid; idx < 64 * 64; idx += 256) {
            int e = e0 + (idx & 63);
            int f = idx >> 6;
            if (e < E_)
                g_xt[((size_t)b * E_ + e) * F_ + f] = x[((size_t)b * F_ + f) * E_ + e];
        }
    }
}

// ---------------------------------------------------------------------------
// Persistent tcgen05 kernel: W in TMEM once, loop tiles (gather -> MMA -> epi)
// ---------------------------------------------------------------------------
__global__ __launch_bounds__(NT_, 1)
void meshconv_tc(const void*  __restrict__ gemm_raw,
                 const float* __restrict__ Wg,
                 const float* __restrict__ bias,
                 float*       __restrict__ out)
{
#if TC_OK_
    extern __shared__ char smem[];
    uint32_t sbase = smem_u32(smem);
    char* tile = smem + 1024;          // G tile / W staging
    uint32_t mbar = sbase + 8;
    uint32_t gsb  = sbase + 1024;

    const int tid = threadIdx.x, wid = tid >> 5, lane = tid & 31;

    if (wid == 0) {
        TC_ALLOC(sbase, 512);
        TC_RELINQ();
        if (elect1()) MB_INIT(mbar, 1);
    }
    __syncthreads();
    uint32_t tmem;
    asm volatile("ld.shared.b32 %0, [%1];" : "=r"(tmem) : "r"(sbase));

    // ---- stage W: gmem -> smem (reorder kappa = f*5+q  ->  kappa' = q*64+f) ----
    float* ws = (float*)tile;
    #pragma unroll 4
    for (int i = 0; i < 40; i++) {
        int idx4 = tid + i * 256;                 // 10240 float4 total
        int o = idx4 / 80, c4 = idx4 % 80;
        float4 v = *(const float4*)(Wg + o * KK_ + c4 * 4);
        int kk = c4 * 4;
        ws[o * WS_STR_ + ((kk    ) % 5) * 64 + (kk    ) / 5] = v.x;
        ws[o * WS_STR_ + ((kk + 1) % 5) * 64 + (kk + 1) / 5] = v.y;
        ws[o * WS_STR_ + ((kk + 2) % 5) * 64 + (kk + 2) / 5] = v.z;
        ws[o * WS_STR_ + ((kk + 3) % 5) * 64 + (kk + 3) / 5] = v.w;
    }
    __syncthreads();

    // ---- smem -> TMEM (A operand, tf32, lane = Cout row, col = kappa') ----
    if (tid < 128) {
        const float* wrow = ws + tid * WS_STR_;
        uint32_t woff = (uint32_t)(wid & 3) << 21;
        for (int g = 0; g < 10; g++) {
            uint32_t r[32];
            #pragma unroll
            for (int u = 0; u < 8; u++) {
                float4 v = *(const float4*)(wrow + g * 32 + u * 4);
                asm("cvt.rna.tf32.f32 %0, %1;" : "=r"(r[u*4+0]) : "f"(v.x));
                asm("cvt.rna.tf32.f32 %0, %1;" : "=r"(r[u*4+1]) : "f"(v.y));
                asm("cvt.rna.tf32.f32 %0, %1;" : "=r"(r[u*4+2]) : "f"(v.z));
                asm("cvt.rna.tf32.f32 %0, %1;" : "=r"(r[u*4+3]) : "f"(v.w));
            }
            TC_ST_X32(tmem + TMEM_A_ + g * 32 + woff, r);
            TC_WAIT_ST();
        }
    }
    TC_FENCE_BEFORE();
    __syncthreads();

    // ---- persistent tile loop ----
    int it = 0;
    for (int t = blockIdx.x; t < NTILES_; t += gridDim.x, it++) {
        int b  = t / TILES_PB_;
        int e0 = (t - b * TILES_PB_) * TN_;

        // ---- gather + combine -> G tile in SMEM (tf32, SW128 blocked atoms) ----
        {
            int e = tid & 127, half = tid >> 7;
            int eg = e0 + e; if (eg > E_ - 1) eg = E_ - 1;
            size_t gi = ((size_t)b * E_ + eg) * 4;
            int n1, n2, n3, n4;
            if (g_idx64) {
                const long long* gp = (const long long*)gemm_raw + gi;
                n1 = (int)gp[0]; n2 = (int)gp[1]; n3 = (int)gp[2]; n4 = (int)gp[3];
            } else {
                const int* gp = (const int*)gemm_raw + gi;
                n1 = gp[0]; n2 = gp[1]; n3 = gp[2]; n4 = gp[3];
            }
            const float4* r0 = (const float4*)(g_xt + ((size_t)b * E_ + eg) * F_) + half * 8;
            const float4* r1 = (const float4*)(g_xt + ((size_t)b * E_ + n1) * F_) + half * 8;
            const float4* r2 = (const float4*)(g_xt + ((size_t)b * E_ + n2) * F_) + half * 8;
            const float4* r3 = (const float4*)(g_xt + ((size_t)b * E_ + n3) * F_) + half * 8;
            const float4* r4 = (const float4*)(g_xt + ((size_t)b * E_ + n4) * F_) + half * 8;

            uint32_t obase = (uint32_t)((e >> 3) << 10) + (uint32_t)((e & 7) << 7);
            #pragma unroll
            for (int i = 0; i < 8; i++) {
                float4 v0 = r0[i], v1 = r1[i], v2 = r2[i], v3 = r3[i], v4 = r4[i];
                float4 w0 = make_float4(f2t(v0.x), f2t(v0.y), f2t(v0.z), f2t(v0.w));
                float4 w1 = make_float4(f2t(v1.x+v3.x), f2t(v1.y+v3.y), f2t(v1.z+v3.z), f2t(v1.w+v3.w));
                float4 w2 = make_float4(f2t(v2.x+v4.x), f2t(v2.y+v4.y), f2t(v2.z+v4.z), f2t(v2.w+v4.w));
                float4 w3 = make_float4(f2t(fabsf(v1.x-v3.x)), f2t(fabsf(v1.y-v3.y)),
                                        f2t(fabsf(v1.z-v3.z)), f2t(fabsf(v1.w-v3.w)));
                float4 w4 = make_float4(f2t(fabsf(v2.x-v4.x)), f2t(fabsf(v2.y-v4.y)),
                                        f2t(fabsf(v2.z-v4.z)), f2t(fabsf(v2.w-v4.w)));
                uint32_t oi = obase + (uint32_t)(i << 4);
                #define PUTQ(q, val) do {                                     \
                    uint32_t off = oi + (uint32_t)((2*(q) + half) << 14);     \
                    off = SWZ(off);                                           \
                    *(float4*)(tile + off) = (val);                           \
                } while (0)
                PUTQ(0, w0); PUTQ(1, w1); PUTQ(2, w2); PUTQ(3, w3); PUTQ(4, w4);
                #undef PUTQ
            }
        }
        asm volatile("fence.proxy.async.shared::cta;" ::: "memory");
        __syncthreads();

        // ---- MMA: 40 steps of K=8, single elected thread ----
        if (wid == 0) {
            TC_FENCE_AFTER();
            if (elect1()) {
                uint64_t bb = MAKE_DESC(gsb);
                #pragma unroll 1
                for (int k = 0; k < NSTEP_; k++) {
                    uint64_t bd = bb + (uint64_t)((k >> 2) * 1024 + (k & 3) * 2);
                    mma_tf32_ts(tmem + TMEM_D_, tmem + TMEM_A_ + k * 8, bd, IDESC_, k > 0);
                }
                TC_COMMIT(mbar);
            }
        }

        MB_WAIT_PARITY(mbar, it & 1);
        TC_FENCE_AFTER();

        // ---- epilogue: TMEM D -> bias -> out ----
        {
            int h = wid >> 2;                    // col half: 0 -> cols 0..63, 1 -> 64..127
            int o = (wid & 3) * 32 + lane;       // Cout row (TMEM lane)
            uint32_t r[64];
            TC_LD_X32(r,      tmem + TMEM_D_ + h * 64);
            TC_LD_X32(r + 32, tmem + TMEM_D_ + h * 64 + 32);
            TC_WAIT_LD();
            TC_FENCE_BEFORE();
            float bv = __ldg(bias + o);
            int eb = e0 + h * 64;
            float* po = out + ((size_t)b * CO_ + o) * E_ + eb;
            #pragma unroll
            for (int j = 0; j < 16; j++) {
                float4 v = make_float4(__uint_as_float(r[4*j+0]) + bv,
                                       __uint_as_float(r[4*j+1]) + bv,
                                       __uint_as_float(r[4*j+2]) + bv,
                                       __uint_as_float(r[4*j+3]) + bv);
                if (eb + 4*j + 3 < E_) {
                    *(float4*)(po + 4*j) = v;
                } else {
                    if (eb + 4*j + 0 < E_) po[4*j+0] = v.x;
                    if (eb + 4*j + 1 < E_) po[4*j+1] = v.y;
                    if (eb + 4*j + 2 < E_) po[4*j+2] = v.z;
                    if (eb + 4*j + 3 < E_) po[4*j+3] = v.w;
                }
            }
        }
        __syncthreads();
    }

    // ---- cleanup ----
    if (wid == 0) {
        if (elect1()) MB_INVAL(mbar);
        TC_DEALLOC(tmem, 512);
    }
#endif // TC_OK_
}

// ---------------------------------------------------------------------------
extern "C" void kernel_launch(void* const* d_in, const int* in_sizes, int n_in,
                              void* d_out, int out_size) {
    const float* x    = (const float*)d_in[0];
    const void*  gemm = d_in[1];
    const float* W    = (const float*)d_in[2];
    const float* bias = (const float*)d_in[3];
    float*       out  = (float*)d_out;

    detect_dtype_kernel<<<1, 256>>>((const unsigned int*)gemm);

    dim3 tg((E_ + 63) / 64, B_);
    transpose_kernel<<<tg, 256>>>(x);

    int dev = 0, nsm = 148;
    cudaGetDevice(&dev);
    cudaDeviceGetAttribute(&nsm, cudaDevAttrMultiProcessorCount, dev);
    if (nsm <= 0) nsm = 148;

    int smem_bytes = 1024 + 128 * WS_STR_ * 4;   // 166,912 B (>= G tile 163,840 + 1K hdr)
    cudaFuncSetAttribute(meshconv_tc,
                         cudaFuncAttributeMaxDynamicSharedMemorySize, smem_bytes);
    meshconv_tc<<<nsm, NT_, smem_bytes>>>(gemm, W, bias, out);
}

// round 8
// speedup vs baseline: 4.1154x; 1.3924x over previous
#include <cuda_runtime.h>
#include <stdint.h>

// ---------------- problem constants ----------------
#define B_   8
#define F_   64
#define E_   50000
#define CO_  128
#define KK_  320         // F*5 contraction dim (kappa' = q*64 + f ordering)
#define TN_  128         // edges per tile (MMA N)
#define NT_  256         // threads per CTA
#define TILES_PB_ 391    // ceil(50000/128)
#define NTILES_   (TILES_PB_ * B_)
#define NSTEP_    40     // 320 / 8 (tf32 K per MMA)

#define TMEM_D_  0       // D: cols 0..127
#define TMEM_A_  128     // A: cols 128..447
#define WS_STR_  324     // W smem staging row stride (floats); 324%32==4, 16B-aligned rows
#define HDR_     4096    // smem header (tmem ptr, mbar)

// idesc kind::tf32: c=F32(1<<4), a=TF32(2<<7), b=TF32(2<<10), N=128(16<<17), M=128(8<<24)
#define IDESC_ 0x8200910u

__device__ __align__(16) float g_xt[(size_t)B_ * E_ * F_];   // x transposed (B,E,F)
__device__ int g_idx64;

// Arch-feature gate: tcgen05 only legal in the sm_103a-specific pass.
#if defined(__CUDA_ARCH_FEAT_SM103_ALL)
#define TC_OK_ 1
#else
#define TC_OK_ 0
#endif

// ---------------- PTX helpers (generic) ----------------
__device__ __forceinline__ uint32_t smem_u32(const void* p) {
    uint32_t a;
    asm("{ .reg .u64 t; cvta.to.shared.u64 t, %1; cvt.u32.u64 %0, t; }" : "=r"(a) : "l"(p));
    return a;
}
__device__ __forceinline__ uint32_t elect1() {
    uint32_t p;
    asm volatile("{ .reg .pred p; elect.sync _|p, 0xFFFFFFFF; selp.b32 %0, 1, 0, p; }" : "=r"(p));
    return p;
}
__device__ __forceinline__ float f2t(float x) {   // round-to-nearest tf32
    uint32_t u;
    asm("cvt.rna.tf32.f32 %0, %1;" : "=r"(u) : "f"(x));
    return __uint_as_float(u);
}

#define MB_INIT(mb, c)    asm volatile("mbarrier.init.shared.b64 [%0], %1;" :: "r"(mb), "r"(c) : "memory")
#define MB_INVAL(mb)      asm volatile("mbarrier.inval.shared.b64 [%0];" :: "r"(mb) : "memory")

#define MB_WAIT_PARITY(mb, ph) do {                                          \
    uint32_t _m = (mb), _p = (ph), _d;                                       \
    asm volatile("{ .reg .pred p; mbarrier.try_wait.parity.acquire.cta.shared::cta.b64 p, [%1], %2; selp.b32 %0,1,0,p; }" \
                 : "=r"(_d) : "r"(_m), "r"(_p) : "memory");                  \
    if (!_d) {                                                               \
        asm volatile("{ .reg .pred P1;\n"                                    \
            "WL_%=: mbarrier.try_wait.parity.acquire.cta.shared::cta.b64 P1, [%0], %1, 0x989680;\n" \
            "@P1 bra.uni WD_%=;\n bra.uni WL_%=;\nWD_%=: }"                  \
            :: "r"(_m), "r"(_p) : "memory");                                 \
    } } while (0)

// ---------------- tcgen05 helpers (sm_103a-only) ----------------
#if TC_OK_
#define TC_ALLOC(sa, n)   asm volatile("tcgen05.alloc.cta_group::1.sync.aligned.shared::cta.b32 [%0], %1;" :: "r"(sa), "r"(n) : "memory")
#define TC_RELINQ()       asm volatile("tcgen05.relinquish_alloc_permit.cta_group::1.sync.aligned;")
#define TC_DEALLOC(t, n)  asm volatile("tcgen05.dealloc.cta_group::1.sync.aligned.b32 %0, %1;" :: "r"(t), "r"(n))
#define TC_WAIT_ST()      asm volatile("tcgen05.wait::st.sync.aligned;" ::: "memory")
#define TC_WAIT_LD()      asm volatile("tcgen05.wait::ld.sync.aligned;" ::: "memory")
#define TC_FENCE_BEFORE() asm volatile("tcgen05.fence::before_thread_sync;" ::: "memory")
#define TC_FENCE_AFTER()  asm volatile("tcgen05.fence::after_thread_sync;" ::: "memory")
#define TC_COMMIT(mb)     asm volatile("tcgen05.commit.cta_group::1.mbarrier::arrive::one.shared::cluster.b64 [%0];" :: "r"(mb) : "memory")

#define TC_ST_X32(addr, r) \
    asm volatile("tcgen05.st.sync.aligned.32x32b.x32.b32 [%0], "             \
        "{%1,%2,%3,%4,%5,%6,%7,%8,%9,%10,%11,%12,%13,%14,%15,%16,"          \
        "%17,%18,%19,%20,%21,%22,%23,%24,%25,%26,%27,%28,%29,%30,%31,%32};" \
        :: "r"(addr),                                                        \
        "r"((r)[0]),"r"((r)[1]),"r"((r)[2]),"r"((r)[3]),"r"((r)[4]),"r"((r)[5]),"r"((r)[6]),"r"((r)[7]), \
        "r"((r)[8]),"r"((r)[9]),"r"((r)[10]),"r"((r)[11]),"r"((r)[12]),"r"((r)[13]),"r"((r)[14]),"r"((r)[15]), \
        "r"((r)[16]),"r"((r)[17]),"r"((r)[18]),"r"((r)[19]),"r"((r)[20]),"r"((r)[21]),"r"((r)[22]),"r"((r)[23]), \
        "r"((r)[24]),"r"((r)[25]),"r"((r)[26]),"r"((r)[27]),"r"((r)[28]),"r"((r)[29]),"r"((r)[30]),"r"((r)[31]) \
        : "memory")

#define TC_LD_X32(r, addr) \
    asm volatile("tcgen05.ld.sync.aligned.32x32b.x32.b32 "                   \
        "{%0,%1,%2,%3,%4,%5,%6,%7,%8,%9,%10,%11,%12,%13,%14,%15,"           \
        "%16,%17,%18,%19,%20,%21,%22,%23,%24,%25,%26,%27,%28,%29,%30,%31}, [%32];" \
        : "=r"((r)[0]),"=r"((r)[1]),"=r"((r)[2]),"=r"((r)[3]),"=r"((r)[4]),"=r"((r)[5]),"=r"((r)[6]),"=r"((r)[7]), \
        "=r"((r)[8]),"=r"((r)[9]),"=r"((r)[10]),"=r"((r)[11]),"=r"((r)[12]),"=r"((r)[13]),"=r"((r)[14]),"=r"((r)[15]), \
        "=r"((r)[16]),"=r"((r)[17]),"=r"((r)[18]),"=r"((r)[19]),"=r"((r)[20]),"=r"((r)[21]),"=r"((r)[22]),"=r"((r)[23]), \
        "=r"((r)[24]),"=r"((r)[25]),"=r"((r)[26]),"=r"((r)[27]),"=r"((r)[28]),"=r"((r)[29]),"=r"((r)[30]),"=r"((r)[31]) \
        : "r"(addr))

__device__ __forceinline__ void mma_tf32_ts(uint32_t d, uint32_t a, uint64_t bdesc,
                                            uint32_t idesc, bool acc) {
    uint32_t en = acc ? 1u : 0u;
    asm volatile(
        "{\n\t.reg .pred p;\n\tsetp.ne.u32 p, %5, 0;\n\t"
        "tcgen05.mma.cta_group::1.kind::tf32 [%0], [%1], %2, %3, {%4, %4, %4, %4}, p;\n\t}"
        :: "r"(d), "r"(a), "l"(bdesc), "r"(idesc), "r"(0u), "r"(en) : "memory");
}
#endif // TC_OK_

// SW128 smem descriptor: layout=SW128(2), version=1, SBO=64, LBO=1
#define DESC_BASE_ ((2ull << 61) | (1ull << 46) | (64ull << 32) | (1ull << 16))
#define MAKE_DESC(a) (DESC_BASE_ | ((uint64_t)((a) >> 4) & 0x3FFF))
#define SWZ(o) ((o) ^ (((o) >> 3) & 0x70))

// ---------------------------------------------------------------------------
// dtype detect for gemm (int64 silently downcast to int32 by JAX default)
// ---------------------------------------------------------------------------
__global__ void detect_dtype_kernel(const unsigned int* __restrict__ g) {
    __shared__ int s_nz;
    if (threadIdx.x == 0) s_nz = 0;
    __syncthreads();
    unsigned acc = 0;
    #pragma unroll
    for (int i = 0; i < 8; i++) acc |= g[(threadIdx.x + i * 256) * 2 + 1];
    if (acc) atomicOr(&s_nz, 1);
    __syncthreads();
    if (threadIdx.x == 0) g_idx64 = (s_nz == 0) ? 1 : 0;
}

// ---------------------------------------------------------------------------
// x (B,F,E) -> xt (B,E,F), 64x64 tiles, float4 both sides
// ---------------------------------------------------------------------------
__global__ __launch_bounds__(256) void transpose_kernel(const float* __restrict__ x) {
    __shared__ float t[64 * 68];
    int b  = blockIdx.y;
    int e0 = blockIdx.x * 64;
    int tid = threadIdx.x;

    if (e0 + 64 <= E_) {
        #pragma unroll
        for (int i = 0; i < 4; i++) {
            int idx = tid + i * 256;
            int f = idx >> 4, c4 = idx & 15;
            float4 v = *(const float4*)(x + ((size_t)b * F_ + f) * E_ + e0 + c4 * 4);
            *(float4*)(&t[f * 68 + c4 * 4]) = v;
        }
        __syncthreads();
        int e  = tid & 63;
        int jb = tid >> 6;
        float* po = g_xt + ((size_t)b * E_ + e0 + e) * F_;
        #pragma unroll
        for (int jj = 0; jj < 4; jj++) {
            int j = jb + jj * 4;
            float4 v = make_float4(t[(j*4+0)*68 + e], t[(j*4+1)*68 + e],
                                   t[(j*4+2)*68 + e], t[(j*4+3)*68 + e]);
            *(float4*)(po + j * 4) = v;
        }
    } else {
        for (int idx = tid; idx < 64 * 64; idx += 256) {
            int e = e0 + (idx & 63);
            int f = idx >> 6;
            if (e < E_)
                g_xt[((size_t)b * E_ + e) * F_ + f] = x[((size_t)b * F_ + f) * E_ + e];
        }
    }
}

// ---------------------------------------------------------------------------
// Persistent tcgen05 kernel: W in TMEM once, loop tiles (gather -> MMA -> epi)
// Gather is chunk-parallel: 16 lanes cover one edge row -> 4 lines per LDG.
// ---------------------------------------------------------------------------
__global__ __launch_bounds__(NT_, 1)
void meshconv_tc(const void*  __restrict__ gemm_raw,
                 const float* __restrict__ Wg,
                 const float* __restrict__ bias,
                 float*       __restrict__ out)
{
#if TC_OK_
    extern __shared__ char smem[];
    uint32_t sbase = smem_u32(smem);
    char* tile = smem + HDR_;          // G tile / W staging
    uint32_t mbar = sbase + 8;
    uint32_t gsb  = sbase + HDR_;

    const int tid = threadIdx.x, wid = tid >> 5, lane = tid & 31;
    const int idx64 = g_idx64;

    if (wid == 0) {
        TC_ALLOC(sbase, 512);
        TC_RELINQ();
        if (elect1()) MB_INIT(mbar, 1);
    }
    __syncthreads();
    uint32_t tmem;
    asm volatile("ld.shared.b32 %0, [%1];" : "=r"(tmem) : "r"(sbase));

    // ---- stage W: gmem -> smem (reorder kappa = f*5+q  ->  kappa' = q*64+f) ----
    float* ws = (float*)tile;
    #pragma unroll 4
    for (int i = 0; i < 40; i++) {
        int idx4 = tid + i * 256;
        int o = idx4 / 80, c4 = idx4 % 80;
        float4 v = *(const float4*)(Wg + o * KK_ + c4 * 4);
        int kk = c4 * 4;
        ws[o * WS_STR_ + ((kk    ) % 5) * 64 + (kk    ) / 5] = v.x;
        ws[o * WS_STR_ + ((kk + 1) % 5) * 64 + (kk + 1) / 5] = v.y;
        ws[o * WS_STR_ + ((kk + 2) % 5) * 64 + (kk + 2) / 5] = v.z;
        ws[o * WS_STR_ + ((kk + 3) % 5) * 64 + (kk + 3) / 5] = v.w;
    }
    __syncthreads();

    // ---- smem -> TMEM (A operand, tf32, lane = Cout row, col = kappa') ----
    if (tid < 128) {
        const float* wrow = ws + tid * WS_STR_;
        uint32_t woff = (uint32_t)(wid & 3) << 21;
        for (int g = 0; g < 10; g++) {
            uint32_t r[32];
            #pragma unroll
            for (int u = 0; u < 8; u++) {
                float4 v = *(const float4*)(wrow + g * 32 + u * 4);
                asm("cvt.rna.tf32.f32 %0, %1;" : "=r"(r[u*4+0]) : "f"(v.x));
                asm("cvt.rna.tf32.f32 %0, %1;" : "=r"(r[u*4+1]) : "f"(v.y));
                asm("cvt.rna.tf32.f32 %0, %1;" : "=r"(r[u*4+2]) : "f"(v.z));
                asm("cvt.rna.tf32.f32 %0, %1;" : "=r"(r[u*4+3]) : "f"(v.w));
            }
            TC_ST_X32(tmem + TMEM_A_ + g * 32 + woff, r);
            TC_WAIT_ST();
        }
    }
    TC_FENCE_BEFORE();
    __syncthreads();

    // ---- persistent tile loop ----
    int it = 0;
    for (int t = blockIdx.x; t < NTILES_; t += gridDim.x, it++) {
        int b  = t / TILES_PB_;
        int e0 = (t - b * TILES_PB_) * TN_;
        const float* xb = g_xt + (size_t)b * E_ * F_;

        // ---- gather + combine -> G tile in SMEM (tf32, SW128 blocked atoms) ----
        // unit u = e*16 + c: 16 consecutive lanes cover the 16 float4-chunks of
        // one edge row -> coalesced LDG (4 lines/warp-instr) for all 5 sources.
        #pragma unroll
        for (int i = 0; i < 8; i++) {
            int u = tid + i * 256;
            int e = u >> 4, c = u & 15;
            int eg = e0 + e; if (eg > E_ - 1) eg = E_ - 1;

            int n1, n2, n3, n4;
            if (idx64) {
                const long long* gp = (const long long*)gemm_raw + ((size_t)b * E_ + eg) * 4;
                n1 = (int)gp[0]; n2 = (int)gp[1]; n3 = (int)gp[2]; n4 = (int)gp[3];
            } else {
                int4 gi = *(const int4*)((const int*)gemm_raw + ((size_t)b * E_ + eg) * 4);
                n1 = gi.x; n2 = gi.y; n3 = gi.z; n4 = gi.w;
            }

            float4 v0 = *((const float4*)(xb + (size_t)eg * F_) + c);
            float4 v1 = *((const float4*)(xb + (size_t)n1 * F_) + c);
            float4 v2 = *((const float4*)(xb + (size_t)n2 * F_) + c);
            float4 v3 = *((const float4*)(xb + (size_t)n3 * F_) + c);
            float4 v4 = *((const float4*)(xb + (size_t)n4 * F_) + c);

            float4 w0 = make_float4(f2t(v0.x), f2t(v0.y), f2t(v0.z), f2t(v0.w));
            float4 w1 = make_float4(f2t(v1.x+v3.x), f2t(v1.y+v3.y), f2t(v1.z+v3.z), f2t(v1.w+v3.w));
            float4 w2 = make_float4(f2t(v2.x+v4.x), f2t(v2.y+v4.y), f2t(v2.z+v4.z), f2t(v2.w+v4.w));
            float4 w3 = make_float4(f2t(fabsf(v1.x-v3.x)), f2t(fabsf(v1.y-v3.y)),
                                    f2t(fabsf(v1.z-v3.z)), f2t(fabsf(v1.w-v3.w)));
            float4 w4 = make_float4(f2t(fabsf(v2.x-v4.x)), f2t(fabsf(v2.y-v4.y)),
                                    f2t(fabsf(v2.z-v4.z)), f2t(fabsf(v2.w-v4.w)));

            int half = c >> 3, i4 = c & 7;
            uint32_t obase = ((uint32_t)(e >> 3) << 10) + ((uint32_t)(e & 7) << 7)
                           + ((uint32_t)i4 << 4);
            #define PUTQ(q, val) do {                                         \
                uint32_t off = obase + (uint32_t)((2*(q) + half) << 14);      \
                off = SWZ(off);                                               \
                *(float4*)(tile + off) = (val);                               \
            } while (0)
            PUTQ(0, w0); PUTQ(1, w1); PUTQ(2, w2); PUTQ(3, w3); PUTQ(4, w4);
            #undef PUTQ
        }
        asm volatile("fence.proxy.async.shared::cta;" ::: "memory");
        __syncthreads();

        // ---- MMA: 40 steps of K=8, single elected thread ----
        if (wid == 0) {
            TC_FENCE_AFTER();
            if (elect1()) {
                uint64_t bb = MAKE_DESC(gsb);
                #pragma unroll 1
                for (int k = 0; k < NSTEP_; k++) {
                    uint64_t bd = bb + (uint64_t)((k >> 2) * 1024 + (k & 3) * 2);
                    mma_tf32_ts(tmem + TMEM_D_, tmem + TMEM_A_ + k * 8, bd, IDESC_, k > 0);
                }
                TC_COMMIT(mbar);
            }
        }

        MB_WAIT_PARITY(mbar, it & 1);
        TC_FENCE_AFTER();

        // ---- epilogue: TMEM D -> bias -> out ----
        {
            int h = wid >> 2;                    // col half
            int o = (wid & 3) * 32 + lane;       // Cout row (TMEM lane)
            uint32_t r[64];
            TC_LD_X32(r,      tmem + TMEM_D_ + h * 64);
            TC_LD_X32(r + 32, tmem + TMEM_D_ + h * 64 + 32);
            TC_WAIT_LD();
            TC_FENCE_BEFORE();
            float bv = __ldg(bias + o);
            int eb = e0 + h * 64;
            float* po = out + ((size_t)b * CO_ + o) * E_ + eb;
            #pragma unroll
            for (int j = 0; j < 16; j++) {
                float4 v = make_float4(__uint_as_float(r[4*j+0]) + bv,
                                       __uint_as_float(r[4*j+1]) + bv,
                                       __uint_as_float(r[4*j+2]) + bv,
                                       __uint_as_float(r[4*j+3]) + bv);
                if (eb + 4*j + 3 < E_) {
                    *(float4*)(po + 4*j) = v;
                } else {
                    if (eb + 4*j + 0 < E_) po[4*j+0] = v.x;
                    if (eb + 4*j + 1 < E_) po[4*j+1] = v.y;
                    if (eb + 4*j + 2 < E_) po[4*j+2] = v.z;
                    if (eb + 4*j + 3 < E_) po[4*j+3] = v.w;
                }
            }
        }
        // no trailing sync: next gather writes smem only after per-warp epilogue;
        // pre-MMA __syncthreads orders all warps' gather AND epilogue before MMA.
    }

    // ---- cleanup ----
    __syncthreads();
    if (wid == 0) {
        if (elect1()) MB_INVAL(mbar);
        TC_DEALLOC(tmem, 512);
    }
#endif // TC_OK_
}

// ---------------------------------------------------------------------------
extern "C" void kernel_launch(void* const* d_in, const int* in_sizes, int n_in,
                              void* d_out, int out_size) {
    const float* x    = (const float*)d_in[0];
    const void*  gemm = d_in[1];
    const float* W    = (const float*)d_in[2];
    const float* bias = (const float*)d_in[3];
    float*       out  = (float*)d_out;

    detect_dtype_kernel<<<1, 256>>>((const unsigned int*)gemm);

    dim3 tg((E_ + 63) / 64, B_);
    transpose_kernel<<<tg, 256>>>(x);

    int dev = 0, nsm = 148;
    cudaGetDevice(&dev);
    cudaDeviceGetAttribute(&nsm, cudaDevAttrMultiProcessorCount, dev);
    if (nsm <= 0) nsm = 148;

    int smem_bytes = HDR_ + 128 * WS_STR_ * 4;   // 169,984 B (>= G tile 163,840 + hdr)
    cudaFuncSetAttribute(meshconv_tc,
                         cudaFuncAttributeMaxDynamicSharedMemorySize, smem_bytes);
    meshconv_tc<<<nsm, NT_, smem_bytes>>>(gemm, W, bias, out);
}